// round 11
// baseline (speedup 1.0000x reference)
#include <cuda_runtime.h>
#include <cuda_fp16.h>
#include <math.h>
#include <stdint.h>

#define N_NODES 16000
#define N_EDGES 64000
#define HH 90
#define F0 16
#define EF 8
#define NGR 512
#define H2 45
#define CAP 64
#define NCP_MAX 8192
#define KP_MAX 96

// ---------------- scratch (__device__ globals; no allocation) ----------------
__device__ float g_X0[N_NODES * F0];
__device__ float g_bufA[N_NODES * HH];
__device__ float g_bufB[N_NODES * HH];
__device__ float g_msg[(size_t)N_EDGES * HH];                 // 23 MB
__device__ __half g_G[(size_t)N_NODES * NCP_MAX];             // 262 MB (fp16)
__device__ __half g_Ah[N_NODES * KP_MAX];                     // padded half A
__device__ __half g_BTh[NCP_MAX * KP_MAX];                    // padded half B^T
__device__ float g_agg[N_NODES * HH];                         // overflow-only accumulator (kept zero)
__device__ float g_pool[NGR * H2];
__device__ int   g_deg[N_NODES],  g_bucket[N_NODES * CAP];    // src buckets
__device__ int   g_deg2[N_NODES], g_bucket2[N_NODES * CAP];   // dst buckets
__device__ int   g_ovfS[N_EDGES], g_ovfD[N_EDGES];
__device__ int   g_ovfnS, g_ovfnD;

__device__ __forceinline__ uint32_t smem_u32(const void* p) {
    return (uint32_t)__cvta_generic_to_shared(p);
}
__device__ __forceinline__ void cp16(uint32_t dst, const void* src) {
    asm volatile("cp.async.cg.shared.global [%0], [%1], 16;" :: "r"(dst), "l"(src));
}

// ---------------- fused init: X0 build + deg/pool/counter reset ----------------
__global__ void initA(const float* __restrict__ x, const float* __restrict__ pos) {
    int i = blockIdx.x * blockDim.x + threadIdx.x;
    if (i < N_NODES * F0) {
        int n = i / F0, c = i % F0;
        g_X0[i] = (c < 13) ? x[n * 13 + c] : pos[n * 3 + (c - 13)];
    }
    if (i < N_NODES) { g_deg[i] = 0; g_deg2[i] = 0; }
    if (i < NGR * H2) g_pool[i] = 0.f;
    if (i == 0) { g_ovfnS = 0; g_ovfnD = 0; }
}

__global__ void bucket_build(const int* __restrict__ ei) {
    int e = blockIdx.x * blockDim.x + threadIdx.x;
    if (e >= N_EDGES) return;
    int s = ei[e];
    int slot = atomicAdd(&g_deg[s], 1);
    if (slot < CAP) g_bucket[s * CAP + slot] = e;
    else            g_ovfS[atomicAdd(&g_ovfnS, 1)] = e;
    int t = ei[N_EDGES + e];
    int slot2 = atomicAdd(&g_deg2[t], 1);
    if (slot2 < CAP) g_bucket2[t * CAP + slot2] = e;
    else             g_ovfD[atomicAdd(&g_ovfnD, 1)] = e;
}

// fused operand prep: padded half A  +  half BT (w2 perm + b2 extra cols)
__global__ void prep(const float* __restrict__ Xin,
                     const float* __restrict__ w2, const float* __restrict__ b2,
                     __half* __restrict__ Ah, __half* __restrict__ BTh,
                     int in_c, int out_c, int ncp, int kp) {
    int idx = blockIdx.x * blockDim.x + threadIdx.x;
    int na = N_NODES * kp;
    if (idx < na) {
        int n = idx / kp, k = idx - n * kp;
        Ah[idx] = __float2half((k < in_c) ? Xin[n * in_c + k] : 0.f);
        return;
    }
    idx -= na;
    if (idx >= ncp * kp) return;
    int col = idx / kp, k = idx - col * kp;
    float v = 0.f;
    if (k < in_c) {
        if (col < HH * out_c) {
            int kk = col / out_c, o = col - kk * out_c;
            v = w2[((size_t)kk * in_c + k) * out_c + o];
        } else if (col < HH * out_c + out_c) {
            v = b2[k * out_c + (col - HH * out_c)];
        }
    }
    BTh[idx] = __float2half(v);
}

// ---------------- fp16 mma.sync GEMM (single-shot cp.async): G = Ah @ BTh^T ----------------
__global__ __launch_bounds__(256)
void mma_gemm_h(const __half* __restrict__ A, const __half* __restrict__ BT,
                __half* __restrict__ C, int ncp, int kp, int lda) {
    extern __shared__ __half sm[];
    __half* As = sm;
    __half* Bs = sm + 128 * lda;

    const int tid = threadIdx.x;
    const int lane = tid & 31, wid = tid >> 5;
    const int rowBase = blockIdx.y * 128, colBase = blockIdx.x * 128;
    const int warpRow = (wid & 3) * 32;
    const int warpCol = (wid >> 2) * 64;
    const int qr = lane >> 2, qk = lane & 3;

    const int nvec = kp >> 3;
    for (int t = tid; t < 128 * nvec; t += 256) {
        int row = t / nvec, j = (t - row * nvec) * 8;
        cp16(smem_u32(&As[row * lda + j]), &A[(size_t)(rowBase + row) * kp + j]);
    }
    for (int t = tid; t < 128 * nvec; t += 256) {
        int row = t / nvec, j = (t - row * nvec) * 8;
        cp16(smem_u32(&Bs[row * lda + j]), &BT[(size_t)(colBase + row) * kp + j]);
    }
    asm volatile("cp.async.commit_group;");

    float acc[2][8][4];
#pragma unroll
    for (int mt = 0; mt < 2; mt++)
#pragma unroll
        for (int nt = 0; nt < 8; nt++)
#pragma unroll
            for (int j = 0; j < 4; j++) acc[mt][nt][j] = 0.f;

    asm volatile("cp.async.wait_group 0;");
    __syncthreads();

    for (int ks = 0; ks < kp; ks += 16) {
        uint32_t a[2][4];
#pragma unroll
        for (int mt = 0; mt < 2; mt++) {
            int r = warpRow + mt * 16 + qr;
            a[mt][0] = *(const uint32_t*)&As[r * lda + ks + 2 * qk];
            a[mt][1] = *(const uint32_t*)&As[(r + 8) * lda + ks + 2 * qk];
            a[mt][2] = *(const uint32_t*)&As[r * lda + ks + 2 * qk + 8];
            a[mt][3] = *(const uint32_t*)&As[(r + 8) * lda + ks + 2 * qk + 8];
        }
#pragma unroll
        for (int nt = 0; nt < 8; nt++) {
            int c = warpCol + nt * 8 + qr;
            uint32_t b0 = *(const uint32_t*)&Bs[c * lda + ks + 2 * qk];
            uint32_t b1 = *(const uint32_t*)&Bs[c * lda + ks + 2 * qk + 8];
#pragma unroll
            for (int mt = 0; mt < 2; mt++) {
                asm volatile(
                    "mma.sync.aligned.m16n8k16.row.col.f32.f16.f16.f32 "
                    "{%0,%1,%2,%3}, {%4,%5,%6,%7}, {%8,%9}, {%0,%1,%2,%3};"
                    : "+f"(acc[mt][nt][0]), "+f"(acc[mt][nt][1]),
                      "+f"(acc[mt][nt][2]), "+f"(acc[mt][nt][3])
                    : "r"(a[mt][0]), "r"(a[mt][1]), "r"(a[mt][2]), "r"(a[mt][3]),
                      "r"(b0), "r"(b1));
            }
        }
    }

#pragma unroll
    for (int mt = 0; mt < 2; mt++) {
        int r = rowBase + warpRow + mt * 16 + qr;
#pragma unroll
        for (int nt = 0; nt < 8; nt++) {
            int c = colBase + warpCol + nt * 8 + qk * 2;
            __half2 v0 = __floats2half2_rn(acc[mt][nt][0], acc[mt][nt][1]);
            __half2 v1 = __floats2half2_rn(acc[mt][nt][2], acc[mt][nt][3]);
            *(__half2*)&C[(size_t)r * ncp + c] = v0;
            *(__half2*)&C[(size_t)(r + 8) * ncp + c] = v1;
        }
    }
}

// ---------------- per-src-node: edge MLP + message (vectorized LDS) ----------------
__global__ void msg2(const int* __restrict__ ei, const float* __restrict__ ea,
                     const float* __restrict__ w1, const float* __restrict__ b1,
                     int out_c, int strideG,
                     const __half* __restrict__ G, float* __restrict__ msg) {
    int n = blockIdx.x;
    int d = g_deg[n];
    if (d == 0) return;
    if (d > CAP) d = CAP;
    __shared__ __align__(16) __half Gs[NCP_MAX];     // 16 KB
    __shared__ __align__(16) float hs[8][92];        // padded; cols 90,91 stay zero
    __shared__ __align__(16) float w1s[EF][HH];
    __shared__ float b1s[HH];
    __shared__ float eas[8][EF];
    __shared__ int eS[8];
    int tid = threadIdx.x;

    const __half* Grow = &G[(size_t)n * strideG];
    int nvec = (HH * out_c + out_c + 7) >> 3;
    for (int t = tid; t < nvec; t += blockDim.x)
        *(uint4*)&Gs[t * 8] = *(const uint4*)&Grow[t * 8];
    for (int t = tid; t < EF * HH; t += blockDim.x) w1s[t / HH][t % HH] = w1[t];
    for (int t = tid; t < HH; t += blockDim.x) b1s[t] = b1[t];
    if (tid < 16) hs[tid >> 1][90 + (tid & 1)] = 0.f;
    __syncthreads();
    float xbv = (tid < out_c) ? __half2float(Gs[HH * out_c + tid]) : 0.f;

    for (int base = 0; base < d; base += 8) {
        int m = min(8, d - base);
        __syncthreads();
        if (tid < m) eS[tid] = g_bucket[n * CAP + base + tid];
        __syncthreads();
        for (int t = tid; t < m * EF; t += blockDim.x)
            eas[t >> 3][t & 7] = ea[eS[t >> 3] * EF + (t & 7)];
        __syncthreads();
        int k = tid;
        if (k < HH) {
            for (int j = 0; j < m; j++) {
                float s = b1s[k];
#pragma unroll
                for (int q = 0; q < EF; q++) s = fmaf(eas[j][q], w1s[q][k], s);
                hs[j][k] = fmaxf(s, 0.f);
            }
        }
        __syncthreads();
        int o = tid;
        if (o < out_c) {
            float acc[8];
#pragma unroll
            for (int j = 0; j < 8; j++) acc[j] = 0.f;
            for (int kb = 0; kb < 88; kb += 4) {
                float g0 = __half2float(Gs[(kb + 0) * out_c + o]);
                float g1 = __half2float(Gs[(kb + 1) * out_c + o]);
                float g2 = __half2float(Gs[(kb + 2) * out_c + o]);
                float g3 = __half2float(Gs[(kb + 3) * out_c + o]);
#pragma unroll
                for (int j = 0; j < 8; j++) {
                    float4 h4 = *(const float4*)&hs[j][kb];
                    acc[j] = fmaf(h4.x, g0, acc[j]);
                    acc[j] = fmaf(h4.y, g1, acc[j]);
                    acc[j] = fmaf(h4.z, g2, acc[j]);
                    acc[j] = fmaf(h4.w, g3, acc[j]);
                }
            }
#pragma unroll
            for (int kk = 88; kk < 90; kk++) {
                float g = __half2float(Gs[kk * out_c + o]);
#pragma unroll
                for (int j = 0; j < 8; j++) acc[j] = fmaf(hs[j][kk], g, acc[j]);
            }
            for (int j = 0; j < m; j++)
                msg[(size_t)eS[j] * out_c + o] = acc[j] + xbv;
        }
    }
}

// src-overflow fallback (normally zero iterations)
__global__ void msg_ovfS(const int* __restrict__ ei, const float* __restrict__ ea,
                         const float* __restrict__ w1, const float* __restrict__ b1,
                         int out_c, int strideG,
                         const __half* __restrict__ G, float* __restrict__ msg) {
    __shared__ float hs[HH];
    for (int idx = blockIdx.x; idx < g_ovfnS; idx += gridDim.x) {
        int e = g_ovfS[idx];
        int n = ei[e];
        int k = threadIdx.x;
        if (k < HH) {
            float s = b1[k];
#pragma unroll
            for (int q = 0; q < EF; q++) s = fmaf(ea[e * EF + q], w1[q * HH + k], s);
            hs[k] = fmaxf(s, 0.f);
        }
        __syncthreads();
        const __half* Grow = &G[(size_t)n * strideG];
        int o = threadIdx.x;
        if (o < out_c) {
            float acc = __half2float(Grow[HH * out_c + o]);
            for (int kk = 0; kk < HH; kk++)
                acc = fmaf(hs[kk], __half2float(Grow[kk * out_c + o]), acc);
            msg[(size_t)e * out_c + o] = acc;
        }
        __syncthreads();
    }
}

// dst-overflow fallback (normally zero iterations)
__global__ void agg_ovfD(const int* __restrict__ ei, int out_c,
                         const float* __restrict__ msg, float* __restrict__ agg) {
    for (int idx = blockIdx.x; idx < g_ovfnD; idx += gridDim.x) {
        int e = g_ovfD[idx];
        int t = ei[N_EDGES + e];
        int o = threadIdx.x;
        if (o < out_c) atomicAdd(&agg[t * out_c + o], msg[(size_t)e * out_c + o]);
    }
}

// per-dst-node: gather + root + bias + relu; restores agg to zero after use
__global__ void aggfin(const float* __restrict__ Xin, float* __restrict__ Xout,
                       const float* __restrict__ root, const float* __restrict__ bias,
                       float* __restrict__ agg, const float* __restrict__ msg,
                       int in_c, int out_c,
                       const int* __restrict__ batch, float* __restrict__ pool) {
    int n = blockIdx.x;
    __shared__ float xs[HH];
    __shared__ int eS[CAP];
    int tid = threadIdx.x;
    for (int t = tid; t < in_c; t += blockDim.x) xs[t] = Xin[n * in_c + t];
    int d = g_deg2[n];
    if (d > CAP) d = CAP;
    for (int t = tid; t < d; t += blockDim.x) eS[t] = g_bucket2[n * CAP + t];
    __syncthreads();
    int o = tid;
    if (o < out_c) {
        float acc = agg[n * out_c + o] + bias[o];
        agg[n * out_c + o] = 0.f;      // restore invariant (replaces zero_f launch)
        for (int j = 0; j < d; j++)
            acc += msg[(size_t)eS[j] * out_c + o];
        for (int i = 0; i < in_c; i++)
            acc = fmaf(xs[i], __ldg(&root[i * out_c + o]), acc);
        acc = fmaxf(acc, 0.f);
        if (pool) atomicAdd(&pool[batch[n] * out_c + o], acc);
        else      Xout[n * out_c + o] = acc;
    }
}

__global__ void head_k(const float* __restrict__ fc1w, const float* __restrict__ fc1b,
                       const float* __restrict__ outw, const float* __restrict__ outb,
                       float* __restrict__ out) {
    int g = blockIdx.x;
    __shared__ float ps[H2];
    __shared__ float fs[HH];
    for (int t = threadIdx.x; t < H2; t += blockDim.x) ps[t] = g_pool[g * H2 + t];
    __syncthreads();
    int o = threadIdx.x;
    if (o < HH) {
        float a = fc1b[o];
        for (int i = 0; i < H2; i++) a = fmaf(ps[i], fc1w[i * HH + o], a);
        fs[o] = fmaxf(a, 0.f);
    }
    __syncthreads();
    if (threadIdx.x == 0) {
        float s = outb[0];
        for (int q = 0; q < HH; q++) s = fmaf(fs[q], outw[q], s);
        out[g] = s;
    }
}

// ---------------- host orchestration ----------------
static void run_layer(const float* Xin, float* Xout, int in_c, int out_c,
                      const float* w1, const float* b1, const float* w2, const float* b2,
                      const float* root, const float* bias,
                      const float* ea, const int* ei,
                      __half* G, __half* Ah, __half* BTh, float* agg, float* msg,
                      const int* batch, float* pool) {
    int ncp = (HH * out_c + out_c + 127) & ~127;   // 8192 / 8192 / 4096
    int kp = ((in_c + 31) & ~31);                  // 32 / 96 / 96
    int lda = kp + 8;

    prep<<<(N_NODES * kp + ncp * kp + 255) / 256, 256>>>(Xin, w2, b2, Ah, BTh,
                                                         in_c, out_c, ncp, kp);
    {
        dim3 gr(ncp / 128, N_NODES / 128);
        size_t smem = (size_t)2 * 128 * lda * sizeof(__half);
        mma_gemm_h<<<gr, 256, smem>>>(Ah, BTh, G, ncp, kp, lda);
    }
    msg2<<<N_NODES, 96>>>(ei, ea, w1, b1, out_c, ncp, G, msg);
    msg_ovfS<<<64, 96>>>(ei, ea, w1, b1, out_c, ncp, G, msg);
    agg_ovfD<<<64, 96>>>(ei, out_c, msg, agg);
    aggfin<<<N_NODES, 96>>>(Xin, Xout, root, bias, agg, msg, in_c, out_c, batch, pool);
}

extern "C" void kernel_launch(void* const* d_in, const int* in_sizes, int n_in,
                              void* d_out, int out_size) {
    const float* x    = (const float*)d_in[0];
    const float* pos  = (const float*)d_in[1];
    const float* ea   = (const float*)d_in[2];
    const int*   ei   = (const int*)  d_in[3];
    const int*   bat  = (const int*)  d_in[4];
    const float* c1w1 = (const float*)d_in[5];
    const float* c1b1 = (const float*)d_in[6];
    const float* c1w2 = (const float*)d_in[7];
    const float* c1b2 = (const float*)d_in[8];
    const float* c1r  = (const float*)d_in[9];
    const float* c1b  = (const float*)d_in[10];
    const float* c2w1 = (const float*)d_in[11];
    const float* c2b1 = (const float*)d_in[12];
    const float* c2w2 = (const float*)d_in[13];
    const float* c2b2 = (const float*)d_in[14];
    const float* c2r  = (const float*)d_in[15];
    const float* c2b  = (const float*)d_in[16];
    const float* c3w1 = (const float*)d_in[17];
    const float* c3b1 = (const float*)d_in[18];
    const float* c3w2 = (const float*)d_in[19];
    const float* c3b2 = (const float*)d_in[20];
    const float* c3r  = (const float*)d_in[21];
    const float* c3b  = (const float*)d_in[22];
    const float* f1w  = (const float*)d_in[23];
    const float* f1b  = (const float*)d_in[24];
    const float* ow   = (const float*)d_in[25];
    const float* ob   = (const float*)d_in[26];
    float* out = (float*)d_out;

    cudaFuncSetAttribute(mma_gemm_h, cudaFuncAttributeMaxDynamicSharedMemorySize,
                         2 * 128 * (KP_MAX + 8) * (int)sizeof(__half));

    void *pX0, *pA, *pB, *pG, *pAh, *pBTh, *pagg, *pmsg, *ppool;
    cudaGetSymbolAddress(&pX0, g_X0);
    cudaGetSymbolAddress(&pA, g_bufA);
    cudaGetSymbolAddress(&pB, g_bufB);
    cudaGetSymbolAddress(&pG, g_G);
    cudaGetSymbolAddress(&pAh, g_Ah);
    cudaGetSymbolAddress(&pBTh, g_BTh);
    cudaGetSymbolAddress(&pagg, g_agg);
    cudaGetSymbolAddress(&pmsg, g_msg);
    cudaGetSymbolAddress(&ppool, g_pool);
    float* X0  = (float*)pX0;
    float* bufA= (float*)pA;
    float* bufB= (float*)pB;
    __half* G  = (__half*)pG;
    __half* Ah = (__half*)pAh;
    __half* BTh= (__half*)pBTh;
    float* agg = (float*)pagg;
    float* msg = (float*)pmsg;
    float* pool= (float*)ppool;

    // launch #1..#3; layer-1 GEMM lands at launch #4 (ncu capture slot)
    initA<<<(N_NODES * F0 + 255) / 256, 256>>>(x, pos);
    bucket_build<<<(N_EDGES + 255) / 256, 256>>>(ei);

    // layer 1: 16 -> 90
    run_layer(X0, bufA, F0, HH, c1w1, c1b1, c1w2, c1b2, c1r, c1b, ea, ei,
              G, Ah, BTh, agg, msg, nullptr, nullptr);
    // layer 2: 90 -> 90
    run_layer(bufA, bufB, HH, HH, c2w1, c2b1, c2w2, c2b2, c2r, c2b, ea, ei,
              G, Ah, BTh, agg, msg, nullptr, nullptr);
    // layer 3: 90 -> 45, fused global_add_pool
    run_layer(bufB, bufA, HH, H2, c3w1, c3b1, c3w2, c3b2, c3r, c3b, ea, ei,
              G, Ah, BTh, agg, msg, bat, pool);

    head_k<<<NGR, 96>>>(f1w, f1b, ow, ob, out);
}

// round 13
// speedup vs baseline: 1.0399x; 1.0399x over previous
#include <cuda_runtime.h>
#include <cuda_fp16.h>
#include <math.h>
#include <stdint.h>

#define N_NODES 16000
#define N_EDGES 64000
#define HH 90
#define F0 16
#define EF 8
#define NGR 512
#define H2 45
#define CAP 64
#define NCP_MAX 8192
#define KP_MAX 96
#define CLEAN_N (NGR * H2 > N_NODES ? NGR * H2 : N_NODES)

// ---------------- scratch (__device__ globals; no allocation) ----------------
// Invariant discipline: deg/deg2/ovfn/pool/agg are zero at module load and are
// restored to zero by their consumers (aggfin) or by cleanup() at the end of
// every kernel_launch, so graph replays always start from the same state.
__device__ float g_X0[N_NODES * F0];
__device__ float g_bufA[N_NODES * HH];
__device__ float g_bufB[N_NODES * HH];
__device__ float g_msg[(size_t)N_EDGES * HH];                 // 23 MB
__device__ __half g_G[(size_t)N_NODES * NCP_MAX];             // 262 MB (fp16)
__device__ __half g_Ah[N_NODES * KP_MAX];                     // padded half A
__device__ __half g_BTh[NCP_MAX * KP_MAX];                    // padded half B^T
__device__ float g_agg[N_NODES * HH];                         // overflow-only accumulator (kept zero)
__device__ float g_pool[NGR * H2];
__device__ int   g_deg[N_NODES],  g_bucket[N_NODES * CAP];    // src buckets
__device__ int   g_deg2[N_NODES], g_bucket2[N_NODES * CAP];   // dst buckets
__device__ int   g_ovfS[N_EDGES], g_ovfD[N_EDGES];
__device__ int   g_ovfnS, g_ovfnD;

__device__ __forceinline__ uint32_t smem_u32(const void* p) {
    return (uint32_t)__cvta_generic_to_shared(p);
}
__device__ __forceinline__ void cp16(uint32_t dst, const void* src) {
    asm volatile("cp.async.cg.shared.global [%0], [%1], 16;" :: "r"(dst), "l"(src));
}

// launch #1: buckets (relies on deg/deg2 == 0 invariant)
__global__ void bucket_build(const int* __restrict__ ei) {
    int e = blockIdx.x * blockDim.x + threadIdx.x;
    if (e >= N_EDGES) return;
    int s = ei[e];
    int slot = atomicAdd(&g_deg[s], 1);
    if (slot < CAP) g_bucket[s * CAP + slot] = e;
    else            g_ovfS[atomicAdd(&g_ovfnS, 1)] = e;
    int t = ei[N_EDGES + e];
    int slot2 = atomicAdd(&g_deg2[t], 1);
    if (slot2 < CAP) g_bucket2[t * CAP + slot2] = e;
    else             g_ovfD[atomicAdd(&g_ovfnD, 1)] = e;
}

// launch #2: layer-1 operand prep — X0(float), Ah(half, kp=32), BT1(half)
__global__ void prep1(const float* __restrict__ x, const float* __restrict__ pos,
                      const float* __restrict__ w2, const float* __restrict__ b2,
                      __half* __restrict__ Ah, __half* __restrict__ BTh,
                      int ncp, int kp) {
    int idx = blockIdx.x * blockDim.x + threadIdx.x;
    int na = N_NODES * kp;
    if (idx < na) {
        int n = idx / kp, k = idx - n * kp;
        float v = 0.f;
        if (k < 13)       v = x[n * 13 + k];
        else if (k < F0)  v = pos[n * 3 + (k - 13)];
        Ah[idx] = __float2half(v);
        if (k < F0) g_X0[n * F0 + k] = v;
        return;
    }
    idx -= na;
    if (idx >= ncp * kp) return;
    int col = idx / kp, k = idx - col * kp;
    float v = 0.f;
    if (k < F0) {
        if (col < HH * HH) {
            int kk = col / HH, o = col - kk * HH;
            v = w2[((size_t)kk * F0 + k) * HH + o];
        } else if (col < HH * HH + HH) {
            v = b2[k * HH + (col - HH * HH)];
        }
    }
    BTh[idx] = __float2half(v);
}

// layers 2/3: fused operand prep — padded half A + half BT (w2 perm + b2 cols)
__global__ void prep(const float* __restrict__ Xin,
                     const float* __restrict__ w2, const float* __restrict__ b2,
                     __half* __restrict__ Ah, __half* __restrict__ BTh,
                     int in_c, int out_c, int ncp, int kp) {
    int idx = blockIdx.x * blockDim.x + threadIdx.x;
    int na = N_NODES * kp;
    if (idx < na) {
        int n = idx / kp, k = idx - n * kp;
        Ah[idx] = __float2half((k < in_c) ? Xin[n * in_c + k] : 0.f);
        return;
    }
    idx -= na;
    if (idx >= ncp * kp) return;
    int col = idx / kp, k = idx - col * kp;
    float v = 0.f;
    if (k < in_c) {
        if (col < HH * out_c) {
            int kk = col / out_c, o = col - kk * out_c;
            v = w2[((size_t)kk * in_c + k) * out_c + o];
        } else if (col < HH * out_c + out_c) {
            v = b2[k * out_c + (col - HH * out_c)];
        }
    }
    BTh[idx] = __float2half(v);
}

// ---------------- fp16 mma.sync GEMM (single-shot cp.async): G = Ah @ BTh^T ----------------
__global__ __launch_bounds__(256)
void mma_gemm_h(const __half* __restrict__ A, const __half* __restrict__ BT,
                __half* __restrict__ C, int ncp, int kp, int lda) {
    extern __shared__ __half sm[];
    __half* As = sm;
    __half* Bs = sm + 128 * lda;

    const int tid = threadIdx.x;
    const int lane = tid & 31, wid = tid >> 5;
    const int rowBase = blockIdx.y * 128, colBase = blockIdx.x * 128;
    const int warpRow = (wid & 3) * 32;
    const int warpCol = (wid >> 2) * 64;
    const int qr = lane >> 2, qk = lane & 3;

    const int nvec = kp >> 3;
    for (int t = tid; t < 128 * nvec; t += 256) {
        int row = t / nvec, j = (t - row * nvec) * 8;
        cp16(smem_u32(&As[row * lda + j]), &A[(size_t)(rowBase + row) * kp + j]);
    }
    for (int t = tid; t < 128 * nvec; t += 256) {
        int row = t / nvec, j = (t - row * nvec) * 8;
        cp16(smem_u32(&Bs[row * lda + j]), &BT[(size_t)(colBase + row) * kp + j]);
    }
    asm volatile("cp.async.commit_group;");

    float acc[2][8][4];
#pragma unroll
    for (int mt = 0; mt < 2; mt++)
#pragma unroll
        for (int nt = 0; nt < 8; nt++)
#pragma unroll
            for (int j = 0; j < 4; j++) acc[mt][nt][j] = 0.f;

    asm volatile("cp.async.wait_group 0;");
    __syncthreads();

    for (int ks = 0; ks < kp; ks += 16) {
        uint32_t a[2][4];
#pragma unroll
        for (int mt = 0; mt < 2; mt++) {
            int r = warpRow + mt * 16 + qr;
            a[mt][0] = *(const uint32_t*)&As[r * lda + ks + 2 * qk];
            a[mt][1] = *(const uint32_t*)&As[(r + 8) * lda + ks + 2 * qk];
            a[mt][2] = *(const uint32_t*)&As[r * lda + ks + 2 * qk + 8];
            a[mt][3] = *(const uint32_t*)&As[(r + 8) * lda + ks + 2 * qk + 8];
        }
#pragma unroll
        for (int nt = 0; nt < 8; nt++) {
            int c = warpCol + nt * 8 + qr;
            uint32_t b0 = *(const uint32_t*)&Bs[c * lda + ks + 2 * qk];
            uint32_t b1 = *(const uint32_t*)&Bs[c * lda + ks + 2 * qk + 8];
#pragma unroll
            for (int mt = 0; mt < 2; mt++) {
                asm volatile(
                    "mma.sync.aligned.m16n8k16.row.col.f32.f16.f16.f32 "
                    "{%0,%1,%2,%3}, {%4,%5,%6,%7}, {%8,%9}, {%0,%1,%2,%3};"
                    : "+f"(acc[mt][nt][0]), "+f"(acc[mt][nt][1]),
                      "+f"(acc[mt][nt][2]), "+f"(acc[mt][nt][3])
                    : "r"(a[mt][0]), "r"(a[mt][1]), "r"(a[mt][2]), "r"(a[mt][3]),
                      "r"(b0), "r"(b1));
            }
        }
    }

#pragma unroll
    for (int mt = 0; mt < 2; mt++) {
        int r = rowBase + warpRow + mt * 16 + qr;
#pragma unroll
        for (int nt = 0; nt < 8; nt++) {
            int c = colBase + warpCol + nt * 8 + qk * 2;
            __half2 v0 = __floats2half2_rn(acc[mt][nt][0], acc[mt][nt][1]);
            __half2 v1 = __floats2half2_rn(acc[mt][nt][2], acc[mt][nt][3]);
            *(__half2*)&C[(size_t)r * ncp + c] = v0;
            *(__half2*)&C[(size_t)(r + 8) * ncp + c] = v1;
        }
    }
}

// ---------------- per-src-node: edge MLP + message (round-9 proven inner loop) ----------------
__global__ void msg2(const int* __restrict__ ei, const float* __restrict__ ea,
                     const float* __restrict__ w1, const float* __restrict__ b1,
                     int out_c, int strideG,
                     const __half* __restrict__ G, float* __restrict__ msg) {
    int n = blockIdx.x;
    int d = g_deg[n];
    if (d == 0) return;
    if (d > CAP) d = CAP;
    __shared__ __align__(16) __half Gs[NCP_MAX];     // 16 KB
    __shared__ float w1s[EF][HH];
    __shared__ float b1s[HH];
    __shared__ float eas[8][EF];
    __shared__ float hs[8][HH];
    __shared__ int eS[8];
    int tid = threadIdx.x;

    const __half* Grow = &G[(size_t)n * strideG];
    int nvec = (HH * out_c + out_c + 7) >> 3;
    for (int t = tid; t < nvec; t += blockDim.x)
        *(uint4*)&Gs[t * 8] = *(const uint4*)&Grow[t * 8];
    for (int t = tid; t < EF * HH; t += blockDim.x) w1s[t / HH][t % HH] = w1[t];
    for (int t = tid; t < HH; t += blockDim.x) b1s[t] = b1[t];
    __syncthreads();
    float xbv = (tid < out_c) ? __half2float(Gs[HH * out_c + tid]) : 0.f;

    for (int base = 0; base < d; base += 8) {
        int m = min(8, d - base);
        __syncthreads();
        if (tid < m) eS[tid] = g_bucket[n * CAP + base + tid];
        __syncthreads();
        for (int t = tid; t < m * EF; t += blockDim.x)
            eas[t >> 3][t & 7] = ea[eS[t >> 3] * EF + (t & 7)];
        __syncthreads();
        int k = tid;
        if (k < HH) {
            for (int j = 0; j < m; j++) {
                float s = b1s[k];
#pragma unroll
                for (int q = 0; q < EF; q++) s = fmaf(eas[j][q], w1s[q][k], s);
                hs[j][k] = fmaxf(s, 0.f);
            }
        }
        __syncthreads();
        int o = tid;
        if (o < out_c) {
            float acc[8];
#pragma unroll
            for (int j = 0; j < 8; j++) acc[j] = 0.f;
            for (int kk = 0; kk < HH; kk++) {
                float g = __half2float(Gs[kk * out_c + o]);
#pragma unroll
                for (int j = 0; j < 8; j++) acc[j] = fmaf(hs[j][kk], g, acc[j]);
            }
            for (int j = 0; j < m; j++)
                msg[(size_t)eS[j] * out_c + o] = acc[j] + xbv;
        }
    }
}

// src-overflow fallback (normally zero iterations)
__global__ void msg_ovfS(const int* __restrict__ ei, const float* __restrict__ ea,
                         const float* __restrict__ w1, const float* __restrict__ b1,
                         int out_c, int strideG,
                         const __half* __restrict__ G, float* __restrict__ msg) {
    __shared__ float hs[HH];
    for (int idx = blockIdx.x; idx < g_ovfnS; idx += gridDim.x) {
        int e = g_ovfS[idx];
        int n = ei[e];
        int k = threadIdx.x;
        if (k < HH) {
            float s = b1[k];
#pragma unroll
            for (int q = 0; q < EF; q++) s = fmaf(ea[e * EF + q], w1[q * HH + k], s);
            hs[k] = fmaxf(s, 0.f);
        }
        __syncthreads();
        const __half* Grow = &G[(size_t)n * strideG];
        int o = threadIdx.x;
        if (o < out_c) {
            float acc = __half2float(Grow[HH * out_c + o]);
            for (int kk = 0; kk < HH; kk++)
                acc = fmaf(hs[kk], __half2float(Grow[kk * out_c + o]), acc);
            msg[(size_t)e * out_c + o] = acc;
        }
        __syncthreads();
    }
}

// dst-overflow fallback (normally zero iterations)
__global__ void agg_ovfD(const int* __restrict__ ei, int out_c,
                         const float* __restrict__ msg, float* __restrict__ agg) {
    for (int idx = blockIdx.x; idx < g_ovfnD; idx += gridDim.x) {
        int e = g_ovfD[idx];
        int t = ei[N_EDGES + e];
        int o = threadIdx.x;
        if (o < out_c) atomicAdd(&agg[t * out_c + o], msg[(size_t)e * out_c + o]);
    }
}

// per-dst-node: gather + root + bias + relu; restores agg to zero after use
__global__ void aggfin(const float* __restrict__ Xin, float* __restrict__ Xout,
                       const float* __restrict__ root, const float* __restrict__ bias,
                       float* __restrict__ agg, const float* __restrict__ msg,
                       int in_c, int out_c,
                       const int* __restrict__ batch, float* __restrict__ pool) {
    int n = blockIdx.x;
    __shared__ float xs[HH];
    __shared__ int eS[CAP];
    int tid = threadIdx.x;
    for (int t = tid; t < in_c; t += blockDim.x) xs[t] = Xin[n * in_c + t];
    int d = g_deg2[n];
    if (d > CAP) d = CAP;
    for (int t = tid; t < d; t += blockDim.x) eS[t] = g_bucket2[n * CAP + t];
    __syncthreads();
    int o = tid;
    if (o < out_c) {
        float acc = agg[n * out_c + o] + bias[o];
        agg[n * out_c + o] = 0.f;      // restore invariant
        for (int j = 0; j < d; j++)
            acc += msg[(size_t)eS[j] * out_c + o];
        for (int i = 0; i < in_c; i++)
            acc = fmaf(xs[i], __ldg(&root[i * out_c + o]), acc);
        acc = fmaxf(acc, 0.f);
        if (pool) atomicAdd(&pool[batch[n] * out_c + o], acc);
        else      Xout[n * out_c + o] = acc;
    }
}

__global__ void head_k(const float* __restrict__ fc1w, const float* __restrict__ fc1b,
                       const float* __restrict__ outw, const float* __restrict__ outb,
                       float* __restrict__ out) {
    int g = blockIdx.x;
    __shared__ float ps[H2];
    __shared__ float fs[HH];
    for (int t = threadIdx.x; t < H2; t += blockDim.x) ps[t] = g_pool[g * H2 + t];
    __syncthreads();
    int o = threadIdx.x;
    if (o < HH) {
        float a = fc1b[o];
        for (int i = 0; i < H2; i++) a = fmaf(ps[i], fc1w[i * HH + o], a);
        fs[o] = fmaxf(a, 0.f);
    }
    __syncthreads();
    if (threadIdx.x == 0) {
        float s = outb[0];
        for (int q = 0; q < HH; q++) s = fmaf(fs[q], outw[q], s);
        out[g] = s;
    }
}

// final launch: restore ALL invariants (grid must cover NGR*H2 for pool!)
__global__ void cleanup() {
    int i = blockIdx.x * blockDim.x + threadIdx.x;
    if (i < N_NODES) { g_deg[i] = 0; g_deg2[i] = 0; }
    if (i < NGR * H2) g_pool[i] = 0.f;
    if (i == 0) { g_ovfnS = 0; g_ovfnD = 0; }
}

// ---------------- host orchestration ----------------
static void run_tail(const float* Xin, float* Xout, int in_c, int out_c, int ncp,
                     const float* w1, const float* b1,
                     const float* root, const float* bias,
                     const float* ea, const int* ei,
                     __half* G, float* agg, float* msg,
                     const int* batch, float* pool) {
    msg2<<<N_NODES, 96>>>(ei, ea, w1, b1, out_c, ncp, G, msg);
    msg_ovfS<<<64, 96>>>(ei, ea, w1, b1, out_c, ncp, G, msg);
    agg_ovfD<<<64, 96>>>(ei, out_c, msg, agg);
    aggfin<<<N_NODES, 96>>>(Xin, Xout, root, bias, agg, msg, in_c, out_c, batch, pool);
}

extern "C" void kernel_launch(void* const* d_in, const int* in_sizes, int n_in,
                              void* d_out, int out_size) {
    const float* x    = (const float*)d_in[0];
    const float* pos  = (const float*)d_in[1];
    const float* ea   = (const float*)d_in[2];
    const int*   ei   = (const int*)  d_in[3];
    const int*   bat  = (const int*)  d_in[4];
    const float* c1w1 = (const float*)d_in[5];
    const float* c1b1 = (const float*)d_in[6];
    const float* c1w2 = (const float*)d_in[7];
    const float* c1b2 = (const float*)d_in[8];
    const float* c1r  = (const float*)d_in[9];
    const float* c1b  = (const float*)d_in[10];
    const float* c2w1 = (const float*)d_in[11];
    const float* c2b1 = (const float*)d_in[12];
    const float* c2w2 = (const float*)d_in[13];
    const float* c2b2 = (const float*)d_in[14];
    const float* c2r  = (const float*)d_in[15];
    const float* c2b  = (const float*)d_in[16];
    const float* c3w1 = (const float*)d_in[17];
    const float* c3b1 = (const float*)d_in[18];
    const float* c3w2 = (const float*)d_in[19];
    const float* c3b2 = (const float*)d_in[20];
    const float* c3r  = (const float*)d_in[21];
    const float* c3b  = (const float*)d_in[22];
    const float* f1w  = (const float*)d_in[23];
    const float* f1b  = (const float*)d_in[24];
    const float* ow   = (const float*)d_in[25];
    const float* ob   = (const float*)d_in[26];
    float* out = (float*)d_out;

    cudaFuncSetAttribute(mma_gemm_h, cudaFuncAttributeMaxDynamicSharedMemorySize,
                         2 * 128 * (KP_MAX + 8) * (int)sizeof(__half));

    void *pX0, *pA, *pB, *pG, *pAh, *pBTh, *pagg, *pmsg, *ppool;
    cudaGetSymbolAddress(&pX0, g_X0);
    cudaGetSymbolAddress(&pA, g_bufA);
    cudaGetSymbolAddress(&pB, g_bufB);
    cudaGetSymbolAddress(&pG, g_G);
    cudaGetSymbolAddress(&pAh, g_Ah);
    cudaGetSymbolAddress(&pBTh, g_BTh);
    cudaGetSymbolAddress(&pagg, g_agg);
    cudaGetSymbolAddress(&pmsg, g_msg);
    cudaGetSymbolAddress(&ppool, g_pool);
    float* X0  = (float*)pX0;
    float* bufA= (float*)pA;
    float* bufB= (float*)pB;
    __half* G  = (__half*)pG;
    __half* Ah = (__half*)pAh;
    __half* BTh= (__half*)pBTh;
    float* agg = (float*)pagg;
    float* msg = (float*)pmsg;
    float* pool= (float*)ppool;

    // ---- layer 1: 16 -> 90  (msg2 is launch #4 → ncu capture slot) ----
    {
        int ncp = 8192, kp = 32, lda = kp + 8;
        bucket_build<<<(N_EDGES + 255) / 256, 256>>>(ei);                       // #1
        prep1<<<(N_NODES * kp + ncp * kp + 255) / 256, 256>>>(x, pos, c1w2, c1b2,
                                                              Ah, BTh, ncp, kp); // #2
        dim3 gr(ncp / 128, N_NODES / 128);
        mma_gemm_h<<<gr, 256, (size_t)2 * 128 * lda * 2>>>(Ah, BTh, G, ncp, kp, lda); // #3
        run_tail(X0, bufA, F0, HH, ncp, c1w1, c1b1, c1r, c1b, ea, ei,
                 G, agg, msg, nullptr, nullptr);                                // #4..#7
    }
    // ---- layer 2: 90 -> 90 ----
    {
        int ncp = 8192, kp = 96, lda = kp + 8;
        prep<<<(N_NODES * kp + ncp * kp + 255) / 256, 256>>>(bufA, c2w2, c2b2,
                                                             Ah, BTh, HH, HH, ncp, kp);
        dim3 gr(ncp / 128, N_NODES / 128);
        mma_gemm_h<<<gr, 256, (size_t)2 * 128 * lda * 2>>>(Ah, BTh, G, ncp, kp, lda);
        run_tail(bufA, bufB, HH, HH, ncp, c2w1, c2b1, c2r, c2b, ea, ei,
                 G, agg, msg, nullptr, nullptr);
    }
    // ---- layer 3: 90 -> 45, fused global_add_pool ----
    {
        int ncp = 4096, kp = 96, lda = kp + 8;
        prep<<<(N_NODES * kp + ncp * kp + 255) / 256, 256>>>(bufB, c3w2, c3b2,
                                                             Ah, BTh, HH, H2, ncp, kp);
        dim3 gr(ncp / 128, N_NODES / 128);
        mma_gemm_h<<<gr, 256, (size_t)2 * 128 * lda * 2>>>(Ah, BTh, G, ncp, kp, lda);
        run_tail(bufB, bufA, HH, H2, ncp, c3w1, c3b1, c3r, c3b, ea, ei,
                 G, agg, msg, bat, pool);
    }

    head_k<<<NGR, 96>>>(f1w, f1b, ow, ob, out);
    cleanup<<<(CLEAN_N + 255) / 256, 256>>>();
}

// round 14
// speedup vs baseline: 1.2221x; 1.1752x over previous
#include <cuda_runtime.h>
#include <cuda_fp16.h>
#include <math.h>
#include <stdint.h>

#define N_NODES 16000
#define N_EDGES 64000
#define HH 90
#define F0 16
#define EF 8
#define NGR 512
#define H2 45
#define CAP 64
#define NCP_MAX 8192
#define KP_MAX 96

// ---------------- scratch (__device__ globals; no allocation) ----------------
__device__ float g_X0[N_NODES * F0];
__device__ float g_bufA[N_NODES * HH];
__device__ float g_bufB[N_NODES * HH];
__device__ float g_msg[(size_t)N_EDGES * HH];                 // 23 MB
__device__ __half g_G[(size_t)N_NODES * NCP_MAX];             // 262 MB (fp16)
__device__ __half g_Ah[N_NODES * KP_MAX];                     // padded half A
__device__ __half g_BTh[NCP_MAX * KP_MAX];                    // padded half B^T
__device__ float g_agg[N_NODES * HH];                         // overflow-only accumulator
__device__ float g_pool[NGR * H2];
__device__ int   g_deg[N_NODES],  g_bucket[N_NODES * CAP];    // src buckets
__device__ int   g_deg2[N_NODES], g_bucket2[N_NODES * CAP];   // dst buckets
__device__ int   g_ovfS[N_EDGES], g_ovfD[N_EDGES];
__device__ int   g_ovfnS, g_ovfnD;

__device__ __forceinline__ uint32_t smem_u32(const void* p) {
    return (uint32_t)__cvta_generic_to_shared(p);
}
__device__ __forceinline__ void cp16(uint32_t dst, const void* src) {
    asm volatile("cp.async.cg.shared.global [%0], [%1], 16;" :: "r"(dst), "l"(src));
}

// ---------------- utility kernels (round-9 proven orchestration) ----------------
__global__ void zero_f(float* p, int n) {
    int i = blockIdx.x * blockDim.x + threadIdx.x;
    if (i < n) p[i] = 0.f;
}

__global__ void init_deg() {
    int i = blockIdx.x * blockDim.x + threadIdx.x;
    if (i < N_NODES) { g_deg[i] = 0; g_deg2[i] = 0; }
    if (i == 0) { g_ovfnS = 0; g_ovfnD = 0; }
}

__global__ void build_x0(const float* __restrict__ x, const float* __restrict__ pos) {
    int i = blockIdx.x * blockDim.x + threadIdx.x;
    if (i >= N_NODES * F0) return;
    int n = i / F0, c = i % F0;
    g_X0[i] = (c < 13) ? x[n * 13 + c] : pos[n * 3 + (c - 13)];
}

__global__ void bucket_build(const int* __restrict__ ei) {
    int e = blockIdx.x * blockDim.x + threadIdx.x;
    if (e >= N_EDGES) return;
    int s = ei[e];
    int slot = atomicAdd(&g_deg[s], 1);
    if (slot < CAP) g_bucket[s * CAP + slot] = e;
    else            g_ovfS[atomicAdd(&g_ovfnS, 1)] = e;
    int t = ei[N_EDGES + e];
    int slot2 = atomicAdd(&g_deg2[t], 1);
    if (slot2 < CAP) g_bucket2[t * CAP + slot2] = e;
    else             g_ovfD[atomicAdd(&g_ovfnD, 1)] = e;
}

// padded half A: Ah[n][k] = (k < in_c) ? Xin[n][k] : 0
__global__ void padX(const float* __restrict__ Xin, __half* __restrict__ Ah,
                     int in_c, int kp) {
    int idx = blockIdx.x * blockDim.x + threadIdx.x;
    if (idx >= N_NODES * kp) return;
    int n = idx / kp, k = idx - n * kp;
    Ah[idx] = __float2half((k < in_c) ? Xin[n * in_c + k] : 0.f);
}

// half BT: cols [0, HH*out) from w2; cols [HH*out, HH*out+out) from b2; else 0
__global__ void buildBT(const float* __restrict__ w2, const float* __restrict__ b2,
                        __half* __restrict__ BT, int in_c, int out_c, int ncp, int kp) {
    int idx = blockIdx.x * blockDim.x + threadIdx.x;
    if (idx >= ncp * kp) return;
    int col = idx / kp, k = idx - col * kp;
    float v = 0.f;
    if (k < in_c) {
        if (col < HH * out_c) {
            int kk = col / out_c, o = col - kk * out_c;
            v = w2[((size_t)kk * in_c + k) * out_c + o];
        } else if (col < HH * out_c + out_c) {
            v = b2[k * out_c + (col - HH * out_c)];
        }
    }
    BT[idx] = __float2half(v);
}

// ---------------- fp16 mma.sync GEMM (single-shot cp.async): G = Ah @ BTh^T ----------------
__global__ __launch_bounds__(256)
void mma_gemm_h(const __half* __restrict__ A, const __half* __restrict__ BT,
                __half* __restrict__ C, int ncp, int kp, int lda) {
    extern __shared__ __half sm[];
    __half* As = sm;
    __half* Bs = sm + 128 * lda;

    const int tid = threadIdx.x;
    const int lane = tid & 31, wid = tid >> 5;
    const int rowBase = blockIdx.y * 128, colBase = blockIdx.x * 128;
    const int warpRow = (wid & 3) * 32;
    const int warpCol = (wid >> 2) * 64;
    const int qr = lane >> 2, qk = lane & 3;

    const int nvec = kp >> 3;
    for (int t = tid; t < 128 * nvec; t += 256) {
        int row = t / nvec, j = (t - row * nvec) * 8;
        cp16(smem_u32(&As[row * lda + j]), &A[(size_t)(rowBase + row) * kp + j]);
    }
    for (int t = tid; t < 128 * nvec; t += 256) {
        int row = t / nvec, j = (t - row * nvec) * 8;
        cp16(smem_u32(&Bs[row * lda + j]), &BT[(size_t)(colBase + row) * kp + j]);
    }
    asm volatile("cp.async.commit_group;");

    float acc[2][8][4];
#pragma unroll
    for (int mt = 0; mt < 2; mt++)
#pragma unroll
        for (int nt = 0; nt < 8; nt++)
#pragma unroll
            for (int j = 0; j < 4; j++) acc[mt][nt][j] = 0.f;

    asm volatile("cp.async.wait_group 0;");
    __syncthreads();

    for (int ks = 0; ks < kp; ks += 16) {
        uint32_t a[2][4];
#pragma unroll
        for (int mt = 0; mt < 2; mt++) {
            int r = warpRow + mt * 16 + qr;
            a[mt][0] = *(const uint32_t*)&As[r * lda + ks + 2 * qk];
            a[mt][1] = *(const uint32_t*)&As[(r + 8) * lda + ks + 2 * qk];
            a[mt][2] = *(const uint32_t*)&As[r * lda + ks + 2 * qk + 8];
            a[mt][3] = *(const uint32_t*)&As[(r + 8) * lda + ks + 2 * qk + 8];
        }
#pragma unroll
        for (int nt = 0; nt < 8; nt++) {
            int c = warpCol + nt * 8 + qr;
            uint32_t b0 = *(const uint32_t*)&Bs[c * lda + ks + 2 * qk];
            uint32_t b1 = *(const uint32_t*)&Bs[c * lda + ks + 2 * qk + 8];
#pragma unroll
            for (int mt = 0; mt < 2; mt++) {
                asm volatile(
                    "mma.sync.aligned.m16n8k16.row.col.f32.f16.f16.f32 "
                    "{%0,%1,%2,%3}, {%4,%5,%6,%7}, {%8,%9}, {%0,%1,%2,%3};"
                    : "+f"(acc[mt][nt][0]), "+f"(acc[mt][nt][1]),
                      "+f"(acc[mt][nt][2]), "+f"(acc[mt][nt][3])
                    : "r"(a[mt][0]), "r"(a[mt][1]), "r"(a[mt][2]), "r"(a[mt][3]),
                      "r"(b0), "r"(b1));
            }
        }
    }

#pragma unroll
    for (int mt = 0; mt < 2; mt++) {
        int r = rowBase + warpRow + mt * 16 + qr;
#pragma unroll
        for (int nt = 0; nt < 8; nt++) {
            int c = colBase + warpCol + nt * 8 + qk * 2;
            __half2 v0 = __floats2half2_rn(acc[mt][nt][0], acc[mt][nt][1]);
            __half2 v1 = __floats2half2_rn(acc[mt][nt][2], acc[mt][nt][3]);
            *(__half2*)&C[(size_t)r * ncp + c] = v0;
            *(__half2*)&C[(size_t)(r + 8) * ncp + c] = v1;
        }
    }
}

// ---------------- per-src-node: edge MLP + message (float2-paired inner loop) ----------------
__global__ void msg2(const int* __restrict__ ei, const float* __restrict__ ea,
                     const float* __restrict__ w1, const float* __restrict__ b1,
                     int out_c, int strideG,
                     const __half* __restrict__ G, float* __restrict__ msg) {
    int n = blockIdx.x;
    int d = g_deg[n];
    if (d == 0) return;
    if (d > CAP) d = CAP;
    __shared__ __align__(16) __half Gs[NCP_MAX];     // 16 KB
    __shared__ __align__(16) float hs[8][HH];        // stride 360 B: float2-safe at even kk
    __shared__ float w1s[EF][HH];
    __shared__ float b1s[HH];
    __shared__ float eas[8][EF];
    __shared__ int eS[8];
    int tid = threadIdx.x;

    const __half* Grow = &G[(size_t)n * strideG];
    int nvec = (HH * out_c + out_c + 7) >> 3;
    for (int t = tid; t < nvec; t += blockDim.x)
        *(uint4*)&Gs[t * 8] = *(const uint4*)&Grow[t * 8];
    for (int t = tid; t < EF * HH; t += blockDim.x) w1s[t / HH][t % HH] = w1[t];
    for (int t = tid; t < HH; t += blockDim.x) b1s[t] = b1[t];
    __syncthreads();
    float xbv = (tid < out_c) ? __half2float(Gs[HH * out_c + tid]) : 0.f;

    for (int base = 0; base < d; base += 8) {
        int m = min(8, d - base);
        __syncthreads();
        if (tid < m) eS[tid] = g_bucket[n * CAP + base + tid];
        __syncthreads();
        for (int t = tid; t < m * EF; t += blockDim.x)
            eas[t >> 3][t & 7] = ea[eS[t >> 3] * EF + (t & 7)];
        __syncthreads();
        int k = tid;
        if (k < HH) {
            for (int j = 0; j < m; j++) {
                float s = b1s[k];
#pragma unroll
                for (int q = 0; q < EF; q++) s = fmaf(eas[j][q], w1s[q][k], s);
                hs[j][k] = fmaxf(s, 0.f);
            }
        }
        __syncthreads();
        int o = tid;
        if (o < out_c) {
            float acc[8];
#pragma unroll
            for (int j = 0; j < 8; j++) acc[j] = 0.f;
            for (int kk = 0; kk < HH; kk += 2) {       // HH=90 even: covers all
                float g0 = __half2float(Gs[kk * out_c + o]);
                float g1 = __half2float(Gs[(kk + 1) * out_c + o]);
#pragma unroll
                for (int j = 0; j < 8; j++) {
                    float2 h2 = *(const float2*)&hs[j][kk];
                    acc[j] = fmaf(h2.x, g0, fmaf(h2.y, g1, acc[j]));
                }
            }
            for (int j = 0; j < m; j++)
                msg[(size_t)eS[j] * out_c + o] = acc[j] + xbv;
        }
    }
}

// src-overflow fallback (normally zero iterations)
__global__ void msg_ovfS(const int* __restrict__ ei, const float* __restrict__ ea,
                         const float* __restrict__ w1, const float* __restrict__ b1,
                         int out_c, int strideG,
                         const __half* __restrict__ G, float* __restrict__ msg) {
    __shared__ float hs[HH];
    for (int idx = blockIdx.x; idx < g_ovfnS; idx += gridDim.x) {
        int e = g_ovfS[idx];
        int n = ei[e];
        int k = threadIdx.x;
        if (k < HH) {
            float s = b1[k];
#pragma unroll
            for (int q = 0; q < EF; q++) s = fmaf(ea[e * EF + q], w1[q * HH + k], s);
            hs[k] = fmaxf(s, 0.f);
        }
        __syncthreads();
        const __half* Grow = &G[(size_t)n * strideG];
        int o = threadIdx.x;
        if (o < out_c) {
            float acc = __half2float(Grow[HH * out_c + o]);
            for (int kk = 0; kk < HH; kk++)
                acc = fmaf(hs[kk], __half2float(Grow[kk * out_c + o]), acc);
            msg[(size_t)e * out_c + o] = acc;
        }
        __syncthreads();
    }
}

// dst-overflow fallback (normally zero iterations)
__global__ void agg_ovfD(const int* __restrict__ ei, int out_c,
                         const float* __restrict__ msg, float* __restrict__ agg) {
    for (int idx = blockIdx.x; idx < g_ovfnD; idx += gridDim.x) {
        int e = g_ovfD[idx];
        int t = ei[N_EDGES + e];
        int o = threadIdx.x;
        if (o < out_c) atomicAdd(&agg[t * out_c + o], msg[(size_t)e * out_c + o]);
    }
}

// per-dst-node: gather msgs + root + bias + relu (fused finalize; optional pool)
__global__ void aggfin(const float* __restrict__ Xin, float* __restrict__ Xout,
                       const float* __restrict__ root, const float* __restrict__ bias,
                       const float* __restrict__ agg, const float* __restrict__ msg,
                       int in_c, int out_c,
                       const int* __restrict__ batch, float* __restrict__ pool) {
    int n = blockIdx.x;
    __shared__ float xs[HH];
    __shared__ int eS[CAP];
    int tid = threadIdx.x;
    for (int t = tid; t < in_c; t += blockDim.x) xs[t] = Xin[n * in_c + t];
    int d = g_deg2[n];
    if (d > CAP) d = CAP;
    for (int t = tid; t < d; t += blockDim.x) eS[t] = g_bucket2[n * CAP + t];
    __syncthreads();
    int o = tid;
    if (o < out_c) {
        float acc = agg[n * out_c + o] + bias[o];
        for (int j = 0; j < d; j++)
            acc += msg[(size_t)eS[j] * out_c + o];
        for (int i = 0; i < in_c; i++)
            acc = fmaf(xs[i], __ldg(&root[i * out_c + o]), acc);
        acc = fmaxf(acc, 0.f);
        if (pool) atomicAdd(&pool[batch[n] * out_c + o], acc);
        else      Xout[n * out_c + o] = acc;
    }
}

__global__ void head_k(const float* __restrict__ fc1w, const float* __restrict__ fc1b,
                       const float* __restrict__ outw, const float* __restrict__ outb,
                       float* __restrict__ out) {
    int g = blockIdx.x;
    __shared__ float ps[H2];
    __shared__ float fs[HH];
    for (int t = threadIdx.x; t < H2; t += blockDim.x) ps[t] = g_pool[g * H2 + t];
    __syncthreads();
    int o = threadIdx.x;
    if (o < HH) {
        float a = fc1b[o];
        for (int i = 0; i < H2; i++) a = fmaf(ps[i], fc1w[i * HH + o], a);
        fs[o] = fmaxf(a, 0.f);
    }
    __syncthreads();
    if (threadIdx.x == 0) {
        float s = outb[0];
        for (int q = 0; q < HH; q++) s = fmaf(fs[q], outw[q], s);
        out[g] = s;
    }
}

// ---------------- host orchestration (round-9 proven) ----------------
static void run_layer(const float* Xin, float* Xout, int in_c, int out_c,
                      const float* w1, const float* b1, const float* w2, const float* b2,
                      const float* root, const float* bias,
                      const float* ea, const int* ei,
                      __half* G, __half* Ah, __half* BTh, float* agg, float* msg,
                      const int* batch, float* pool) {
    int ncp = (HH * out_c + out_c + 127) & ~127;   // 8192 / 8192 / 4096
    int kp = ((in_c + 31) & ~31);                  // 32 / 96 / 96
    int lda = kp + 8;

    padX<<<(N_NODES * kp + 255) / 256, 256>>>(Xin, Ah, in_c, kp);
    buildBT<<<(ncp * kp + 255) / 256, 256>>>(w2, b2, BTh, in_c, out_c, ncp, kp);
    {
        dim3 gr(ncp / 128, N_NODES / 128);
        size_t smem = (size_t)2 * 128 * lda * sizeof(__half);
        mma_gemm_h<<<gr, 256, smem>>>(Ah, BTh, G, ncp, kp, lda);
    }
    msg2<<<N_NODES, 96>>>(ei, ea, w1, b1, out_c, ncp, G, msg);
    msg_ovfS<<<64, 96>>>(ei, ea, w1, b1, out_c, ncp, G, msg);
    zero_f<<<(N_NODES * out_c + 255) / 256, 256>>>(agg, N_NODES * out_c);
    agg_ovfD<<<64, 96>>>(ei, out_c, msg, agg);
    aggfin<<<N_NODES, 96>>>(Xin, Xout, root, bias, agg, msg, in_c, out_c, batch, pool);
}

extern "C" void kernel_launch(void* const* d_in, const int* in_sizes, int n_in,
                              void* d_out, int out_size) {
    const float* x    = (const float*)d_in[0];
    const float* pos  = (const float*)d_in[1];
    const float* ea   = (const float*)d_in[2];
    const int*   ei   = (const int*)  d_in[3];
    const int*   bat  = (const int*)  d_in[4];
    const float* c1w1 = (const float*)d_in[5];
    const float* c1b1 = (const float*)d_in[6];
    const float* c1w2 = (const float*)d_in[7];
    const float* c1b2 = (const float*)d_in[8];
    const float* c1r  = (const float*)d_in[9];
    const float* c1b  = (const float*)d_in[10];
    const float* c2w1 = (const float*)d_in[11];
    const float* c2b1 = (const float*)d_in[12];
    const float* c2w2 = (const float*)d_in[13];
    const float* c2b2 = (const float*)d_in[14];
    const float* c2r  = (const float*)d_in[15];
    const float* c2b  = (const float*)d_in[16];
    const float* c3w1 = (const float*)d_in[17];
    const float* c3b1 = (const float*)d_in[18];
    const float* c3w2 = (const float*)d_in[19];
    const float* c3b2 = (const float*)d_in[20];
    const float* c3r  = (const float*)d_in[21];
    const float* c3b  = (const float*)d_in[22];
    const float* f1w  = (const float*)d_in[23];
    const float* f1b  = (const float*)d_in[24];
    const float* ow   = (const float*)d_in[25];
    const float* ob   = (const float*)d_in[26];
    float* out = (float*)d_out;

    cudaFuncSetAttribute(mma_gemm_h, cudaFuncAttributeMaxDynamicSharedMemorySize,
                         2 * 128 * (KP_MAX + 8) * (int)sizeof(__half));

    void *pX0, *pA, *pB, *pG, *pAh, *pBTh, *pagg, *pmsg, *ppool;
    cudaGetSymbolAddress(&pX0, g_X0);
    cudaGetSymbolAddress(&pA, g_bufA);
    cudaGetSymbolAddress(&pB, g_bufB);
    cudaGetSymbolAddress(&pG, g_G);
    cudaGetSymbolAddress(&pAh, g_Ah);
    cudaGetSymbolAddress(&pBTh, g_BTh);
    cudaGetSymbolAddress(&pagg, g_agg);
    cudaGetSymbolAddress(&pmsg, g_msg);
    cudaGetSymbolAddress(&ppool, g_pool);
    float* X0  = (float*)pX0;
    float* bufA= (float*)pA;
    float* bufB= (float*)pB;
    __half* G  = (__half*)pG;
    __half* Ah = (__half*)pAh;
    __half* BTh= (__half*)pBTh;
    float* agg = (float*)pagg;
    float* msg = (float*)pmsg;
    float* pool= (float*)ppool;

    build_x0<<<(N_NODES * F0 + 255) / 256, 256>>>(x, pos);
    init_deg<<<(N_NODES + 255) / 256, 256>>>();
    bucket_build<<<(N_EDGES + 255) / 256, 256>>>(ei);
    zero_f<<<(NGR * H2 + 255) / 256, 256>>>(pool, NGR * H2);

    // layer 1: 16 -> 90
    run_layer(X0, bufA, F0, HH, c1w1, c1b1, c1w2, c1b2, c1r, c1b, ea, ei,
              G, Ah, BTh, agg, msg, nullptr, nullptr);
    // layer 2: 90 -> 90
    run_layer(bufA, bufB, HH, HH, c2w1, c2b1, c2w2, c2b2, c2r, c2b, ea, ei,
              G, Ah, BTh, agg, msg, nullptr, nullptr);
    // layer 3: 90 -> 45, fused global_add_pool
    run_layer(bufB, bufA, HH, H2, c3w1, c3b1, c3w2, c3b2, c3r, c3b, ea, ei,
              G, Ah, BTh, agg, msg, bat, pool);

    head_k<<<NGR, 96>>>(f1w, f1b, ow, ob, out);
}

// round 15
// speedup vs baseline: 1.2370x; 1.0122x over previous
#include <cuda_runtime.h>
#include <cuda_fp16.h>
#include <math.h>
#include <stdint.h>

#define N_NODES 16000
#define N_EDGES 64000
#define HH 90
#define F0 16
#define EF 8
#define NGR 512
#define H2 45
#define CAP 64
#define NCP_MAX 8192
#define KP_MAX 96
#define NCB 4

typedef unsigned long long ull;

// ---------------- scratch (__device__ globals; no allocation) ----------------
__device__ float g_X0[N_NODES * F0];
__device__ float g_bufA[N_NODES * HH];
__device__ float g_bufB[N_NODES * HH];
__device__ float g_msg[(size_t)N_EDGES * HH];                 // 23 MB
__device__ __half g_G[(size_t)N_NODES * NCP_MAX];             // 262 MB (fp16)
__device__ __half g_Ah[N_NODES * KP_MAX];                     // padded half A
__device__ __half g_BTh[NCP_MAX * KP_MAX];                    // padded half B^T
__device__ float g_agg[N_NODES * HH];                         // overflow-only accumulator
__device__ float g_pool[NGR * H2];
__device__ int   g_deg[N_NODES],  g_bucket[N_NODES * CAP];    // src buckets
__device__ int   g_deg2[N_NODES], g_bucket2[N_NODES * CAP];   // dst buckets
__device__ int   g_ovfS[N_EDGES], g_ovfD[N_EDGES];
__device__ int   g_ovfnS, g_ovfnD;

__device__ __forceinline__ uint32_t smem_u32(const void* p) {
    return (uint32_t)__cvta_generic_to_shared(p);
}
__device__ __forceinline__ void cp16(uint32_t dst, const void* src) {
    asm volatile("cp.async.cg.shared.global [%0], [%1], 16;" :: "r"(dst), "l"(src));
}
__device__ __forceinline__ ull packf2(float lo, float hi) {
    ull r; asm("mov.b64 %0, {%1, %2};" : "=l"(r) : "f"(lo), "f"(hi)); return r;
}
__device__ __forceinline__ void fma2(ull& d, ull a, ull b) {
    asm("fma.rn.f32x2 %0, %1, %2, %0;" : "+l"(d) : "l"(a), "l"(b));
}

// ---------------- utility kernels (round-9/14 proven orchestration) ----------------
__global__ void zero_f(float* p, int n) {
    int i = blockIdx.x * blockDim.x + threadIdx.x;
    if (i < n) p[i] = 0.f;
}

__global__ void init_deg() {
    int i = blockIdx.x * blockDim.x + threadIdx.x;
    if (i < N_NODES) { g_deg[i] = 0; g_deg2[i] = 0; }
    if (i == 0) { g_ovfnS = 0; g_ovfnD = 0; }
}

__global__ void build_x0(const float* __restrict__ x, const float* __restrict__ pos) {
    int i = blockIdx.x * blockDim.x + threadIdx.x;
    if (i >= N_NODES * F0) return;
    int n = i / F0, c = i % F0;
    g_X0[i] = (c < 13) ? x[n * 13 + c] : pos[n * 3 + (c - 13)];
}

__global__ void bucket_build(const int* __restrict__ ei) {
    int e = blockIdx.x * blockDim.x + threadIdx.x;
    if (e >= N_EDGES) return;
    int s = ei[e];
    int slot = atomicAdd(&g_deg[s], 1);
    if (slot < CAP) g_bucket[s * CAP + slot] = e;
    else            g_ovfS[atomicAdd(&g_ovfnS, 1)] = e;
    int t = ei[N_EDGES + e];
    int slot2 = atomicAdd(&g_deg2[t], 1);
    if (slot2 < CAP) g_bucket2[t * CAP + slot2] = e;
    else             g_ovfD[atomicAdd(&g_ovfnD, 1)] = e;
}

// padded half A: Ah[n][k] = (k < in_c) ? Xin[n][k] : 0
__global__ void padX(const float* __restrict__ Xin, __half* __restrict__ Ah,
                     int in_c, int kp) {
    int idx = blockIdx.x * blockDim.x + threadIdx.x;
    if (idx >= N_NODES * kp) return;
    int n = idx / kp, k = idx - n * kp;
    Ah[idx] = __float2half((k < in_c) ? Xin[n * in_c + k] : 0.f);
}

// half BT: cols [0, HH*out) from w2; cols [HH*out, HH*out+out) from b2; else 0
__global__ void buildBT(const float* __restrict__ w2, const float* __restrict__ b2,
                        __half* __restrict__ BT, int in_c, int out_c, int ncp, int kp) {
    int idx = blockIdx.x * blockDim.x + threadIdx.x;
    if (idx >= ncp * kp) return;
    int col = idx / kp, k = idx - col * kp;
    float v = 0.f;
    if (k < in_c) {
        if (col < HH * out_c) {
            int kk = col / out_c, o = col - kk * out_c;
            v = w2[((size_t)kk * in_c + k) * out_c + o];
        } else if (col < HH * out_c + out_c) {
            v = b2[k * out_c + (col - HH * out_c)];
        }
    }
    BT[idx] = __float2half(v);
}

// ---------------- fp16 mma.sync GEMM, NCB column blocks per CTA, double-buffered B ----------------
// Ah [M][kp] half zero-padded; BTh [ncp][kp]; M%128==0, ncp%(128*NCB)==0, kp%32==0, kp<=96.
__global__ __launch_bounds__(256)
void mma_gemm_h(const __half* __restrict__ A, const __half* __restrict__ BT,
                __half* __restrict__ C, int ncp, int kp, int lda) {
    extern __shared__ __half sm[];
    __half* As = sm;
    __half* BsBuf[2] = { sm + 128 * lda, sm + 2 * 128 * lda };

    const int tid = threadIdx.x;
    const int lane = tid & 31, wid = tid >> 5;
    const int rowBase = blockIdx.y * 128;
    const int colBase0 = blockIdx.x * (128 * NCB);
    const int warpRow = (wid & 3) * 32;
    const int warpCol = (wid >> 2) * 64;
    const int qr = lane >> 2, qk = lane & 3;
    const int nvec = kp >> 3;

    // stage A (resident for all NCB col blocks) + B(0)
    for (int t = tid; t < 128 * nvec; t += 256) {
        int row = t / nvec, j = (t - row * nvec) * 8;
        cp16(smem_u32(&As[row * lda + j]), &A[(size_t)(rowBase + row) * kp + j]);
    }
    for (int t = tid; t < 128 * nvec; t += 256) {
        int row = t / nvec, j = (t - row * nvec) * 8;
        cp16(smem_u32(&BsBuf[0][row * lda + j]), &BT[(size_t)(colBase0 + row) * kp + j]);
    }
    asm volatile("cp.async.commit_group;");

    for (int cb = 0; cb < NCB; cb++) {
        const __half* Bs = BsBuf[cb & 1];
        asm volatile("cp.async.wait_group 0;");
        __syncthreads();
        // prefetch next B tile while computing this one
        if (cb + 1 < NCB) {
            __half* Bn = BsBuf[(cb + 1) & 1];
            int colB = colBase0 + (cb + 1) * 128;
            for (int t = tid; t < 128 * nvec; t += 256) {
                int row = t / nvec, j = (t - row * nvec) * 8;
                cp16(smem_u32(&Bn[row * lda + j]), &BT[(size_t)(colB + row) * kp + j]);
            }
            asm volatile("cp.async.commit_group;");
        }

        float acc[2][8][4];
#pragma unroll
        for (int mt = 0; mt < 2; mt++)
#pragma unroll
            for (int nt = 0; nt < 8; nt++)
#pragma unroll
                for (int j = 0; j < 4; j++) acc[mt][nt][j] = 0.f;

        for (int ks = 0; ks < kp; ks += 16) {
            uint32_t a[2][4];
#pragma unroll
            for (int mt = 0; mt < 2; mt++) {
                int r = warpRow + mt * 16 + qr;
                a[mt][0] = *(const uint32_t*)&As[r * lda + ks + 2 * qk];
                a[mt][1] = *(const uint32_t*)&As[(r + 8) * lda + ks + 2 * qk];
                a[mt][2] = *(const uint32_t*)&As[r * lda + ks + 2 * qk + 8];
                a[mt][3] = *(const uint32_t*)&As[(r + 8) * lda + ks + 2 * qk + 8];
            }
#pragma unroll
            for (int nt = 0; nt < 8; nt++) {
                int c = warpCol + nt * 8 + qr;
                uint32_t b0 = *(const uint32_t*)&Bs[c * lda + ks + 2 * qk];
                uint32_t b1 = *(const uint32_t*)&Bs[c * lda + ks + 2 * qk + 8];
#pragma unroll
                for (int mt = 0; mt < 2; mt++) {
                    asm volatile(
                        "mma.sync.aligned.m16n8k16.row.col.f32.f16.f16.f32 "
                        "{%0,%1,%2,%3}, {%4,%5,%6,%7}, {%8,%9}, {%0,%1,%2,%3};"
                        : "+f"(acc[mt][nt][0]), "+f"(acc[mt][nt][1]),
                          "+f"(acc[mt][nt][2]), "+f"(acc[mt][nt][3])
                        : "r"(a[mt][0]), "r"(a[mt][1]), "r"(a[mt][2]), "r"(a[mt][3]),
                          "r"(b0), "r"(b1));
                }
            }
        }

        int colBase = colBase0 + cb * 128;
#pragma unroll
        for (int mt = 0; mt < 2; mt++) {
            int r = rowBase + warpRow + mt * 16 + qr;
#pragma unroll
            for (int nt = 0; nt < 8; nt++) {
                int c = colBase + warpCol + nt * 8 + qk * 2;
                __half2 v0 = __floats2half2_rn(acc[mt][nt][0], acc[mt][nt][1]);
                __half2 v1 = __floats2half2_rn(acc[mt][nt][2], acc[mt][nt][3]);
                *(__half2*)&C[(size_t)r * ncp + c] = v0;
                *(__half2*)&C[(size_t)(r + 8) * ncp + c] = v1;
            }
        }
        __syncthreads();
    }
}

// ---------------- per-src-node: edge MLP + message (FFMA2 inner loop) ----------------
__global__ void msg2(const int* __restrict__ ei, const float* __restrict__ ea,
                     const float* __restrict__ w1, const float* __restrict__ b1,
                     int out_c, int strideG,
                     const __half* __restrict__ G, float* __restrict__ msg) {
    int n = blockIdx.x;
    int d = g_deg[n];
    if (d == 0) return;
    if (d > CAP) d = CAP;
    __shared__ __align__(16) __half Gs[NCP_MAX];     // 16 KB
    __shared__ __align__(16) float hs[8][HH];        // stride 360 B: 8B-safe at even kk
    __shared__ float w1s[EF][HH];
    __shared__ float b1s[HH];
    __shared__ float eas[8][EF];
    __shared__ int eS[8];
    int tid = threadIdx.x;

    const __half* Grow = &G[(size_t)n * strideG];
    int nvec = (HH * out_c + out_c + 7) >> 3;
    for (int t = tid; t < nvec; t += blockDim.x)
        *(uint4*)&Gs[t * 8] = *(const uint4*)&Grow[t * 8];
    for (int t = tid; t < EF * HH; t += blockDim.x) w1s[t / HH][t % HH] = w1[t];
    for (int t = tid; t < HH; t += blockDim.x) b1s[t] = b1[t];
    __syncthreads();
    float xbv = (tid < out_c) ? __half2float(Gs[HH * out_c + tid]) : 0.f;

    for (int base = 0; base < d; base += 8) {
        int m = min(8, d - base);
        __syncthreads();
        if (tid < m) eS[tid] = g_bucket[n * CAP + base + tid];
        __syncthreads();
        for (int t = tid; t < m * EF; t += blockDim.x)
            eas[t >> 3][t & 7] = ea[eS[t >> 3] * EF + (t & 7)];
        __syncthreads();
        int k = tid;
        if (k < HH) {
            for (int j = 0; j < m; j++) {
                float s = b1s[k];
#pragma unroll
                for (int q = 0; q < EF; q++) s = fmaf(eas[j][q], w1s[q][k], s);
                hs[j][k] = fmaxf(s, 0.f);
            }
        }
        __syncthreads();
        int o = tid;
        if (o < out_c) {
            ull acc2[8];
#pragma unroll
            for (int j = 0; j < 8; j++) acc2[j] = 0ULL;
            for (int kk = 0; kk < HH; kk += 2) {       // HH=90 even: covers all
                float g0 = __half2float(Gs[kk * out_c + o]);
                float g1 = __half2float(Gs[(kk + 1) * out_c + o]);
                ull gp = packf2(g0, g1);
#pragma unroll
                for (int j = 0; j < 8; j++) {
                    ull h2 = *(const ull*)&hs[j][kk];
                    fma2(acc2[j], h2, gp);
                }
            }
            for (int j = 0; j < m; j++) {
                float lo, hi;
                asm("mov.b64 {%0, %1}, %2;" : "=f"(lo), "=f"(hi) : "l"(acc2[j]));
                msg[(size_t)eS[j] * out_c + o] = lo + hi + xbv;
            }
        }
    }
}

// src-overflow fallback (normally zero iterations)
__global__ void msg_ovfS(const int* __restrict__ ei, const float* __restrict__ ea,
                         const float* __restrict__ w1, const float* __restrict__ b1,
                         int out_c, int strideG,
                         const __half* __restrict__ G, float* __restrict__ msg) {
    __shared__ float hs[HH];
    for (int idx = blockIdx.x; idx < g_ovfnS; idx += gridDim.x) {
        int e = g_ovfS[idx];
        int n = ei[e];
        int k = threadIdx.x;
        if (k < HH) {
            float s = b1[k];
#pragma unroll
            for (int q = 0; q < EF; q++) s = fmaf(ea[e * EF + q], w1[q * HH + k], s);
            hs[k] = fmaxf(s, 0.f);
        }
        __syncthreads();
        const __half* Grow = &G[(size_t)n * strideG];
        int o = threadIdx.x;
        if (o < out_c) {
            float acc = __half2float(Grow[HH * out_c + o]);
            for (int kk = 0; kk < HH; kk++)
                acc = fmaf(hs[kk], __half2float(Grow[kk * out_c + o]), acc);
            msg[(size_t)e * out_c + o] = acc;
        }
        __syncthreads();
    }
}

// dst-overflow fallback (normally zero iterations)
__global__ void agg_ovfD(const int* __restrict__ ei, int out_c,
                         const float* __restrict__ msg, float* __restrict__ agg) {
    for (int idx = blockIdx.x; idx < g_ovfnD; idx += gridDim.x) {
        int e = g_ovfD[idx];
        int t = ei[N_EDGES + e];
        int o = threadIdx.x;
        if (o < out_c) atomicAdd(&agg[t * out_c + o], msg[(size_t)e * out_c + o]);
    }
}

// per-dst-node: gather msgs + root + bias + relu (fused finalize; optional pool)
__global__ void aggfin(const float* __restrict__ Xin, float* __restrict__ Xout,
                       const float* __restrict__ root, const float* __restrict__ bias,
                       const float* __restrict__ agg, const float* __restrict__ msg,
                       int in_c, int out_c,
                       const int* __restrict__ batch, float* __restrict__ pool) {
    int n = blockIdx.x;
    __shared__ float xs[HH];
    __shared__ int eS[CAP];
    int tid = threadIdx.x;
    for (int t = tid; t < in_c; t += blockDim.x) xs[t] = Xin[n * in_c + t];
    int d = g_deg2[n];
    if (d > CAP) d = CAP;
    for (int t = tid; t < d; t += blockDim.x) eS[t] = g_bucket2[n * CAP + t];
    __syncthreads();
    int o = tid;
    if (o < out_c) {
        float acc = agg[n * out_c + o] + bias[o];
        for (int j = 0; j < d; j++)
            acc += msg[(size_t)eS[j] * out_c + o];
        for (int i = 0; i < in_c; i++)
            acc = fmaf(xs[i], __ldg(&root[i * out_c + o]), acc);
        acc = fmaxf(acc, 0.f);
        if (pool) atomicAdd(&pool[batch[n] * out_c + o], acc);
        else      Xout[n * out_c + o] = acc;
    }
}

__global__ void head_k(const float* __restrict__ fc1w, const float* __restrict__ fc1b,
                       const float* __restrict__ outw, const float* __restrict__ outb,
                       float* __restrict__ out) {
    int g = blockIdx.x;
    __shared__ float ps[H2];
    __shared__ float fs[HH];
    for (int t = threadIdx.x; t < H2; t += blockDim.x) ps[t] = g_pool[g * H2 + t];
    __syncthreads();
    int o = threadIdx.x;
    if (o < HH) {
        float a = fc1b[o];
        for (int i = 0; i < H2; i++) a = fmaf(ps[i], fc1w[i * HH + o], a);
        fs[o] = fmaxf(a, 0.f);
    }
    __syncthreads();
    if (threadIdx.x == 0) {
        float s = outb[0];
        for (int q = 0; q < HH; q++) s = fmaf(fs[q], outw[q], s);
        out[g] = s;
    }
}

// ---------------- host orchestration (round-9/14 proven) ----------------
static void run_layer(const float* Xin, float* Xout, int in_c, int out_c,
                      const float* w1, const float* b1, const float* w2, const float* b2,
                      const float* root, const float* bias,
                      const float* ea, const int* ei,
                      __half* G, __half* Ah, __half* BTh, float* agg, float* msg,
                      const int* batch, float* pool) {
    int ncp = (HH * out_c + out_c + 127) & ~127;   // 8192 / 8192 / 4096
    int kp = ((in_c + 31) & ~31);                  // 32 / 96 / 96
    int lda = kp + 8;

    padX<<<(N_NODES * kp + 255) / 256, 256>>>(Xin, Ah, in_c, kp);
    buildBT<<<(ncp * kp + 255) / 256, 256>>>(w2, b2, BTh, in_c, out_c, ncp, kp);
    {
        dim3 gr(ncp / (128 * NCB), N_NODES / 128);
        size_t smem = (size_t)3 * 128 * lda * sizeof(__half);
        mma_gemm_h<<<gr, 256, smem>>>(Ah, BTh, G, ncp, kp, lda);
    }
    msg2<<<N_NODES, 96>>>(ei, ea, w1, b1, out_c, ncp, G, msg);
    msg_ovfS<<<64, 96>>>(ei, ea, w1, b1, out_c, ncp, G, msg);
    zero_f<<<(N_NODES * out_c + 255) / 256, 256>>>(agg, N_NODES * out_c);
    agg_ovfD<<<64, 96>>>(ei, out_c, msg, agg);
    aggfin<<<N_NODES, 96>>>(Xin, Xout, root, bias, agg, msg, in_c, out_c, batch, pool);
}

extern "C" void kernel_launch(void* const* d_in, const int* in_sizes, int n_in,
                              void* d_out, int out_size) {
    const float* x    = (const float*)d_in[0];
    const float* pos  = (const float*)d_in[1];
    const float* ea   = (const float*)d_in[2];
    const int*   ei   = (const int*)  d_in[3];
    const int*   bat  = (const int*)  d_in[4];
    const float* c1w1 = (const float*)d_in[5];
    const float* c1b1 = (const float*)d_in[6];
    const float* c1w2 = (const float*)d_in[7];
    const float* c1b2 = (const float*)d_in[8];
    const float* c1r  = (const float*)d_in[9];
    const float* c1b  = (const float*)d_in[10];
    const float* c2w1 = (const float*)d_in[11];
    const float* c2b1 = (const float*)d_in[12];
    const float* c2w2 = (const float*)d_in[13];
    const float* c2b2 = (const float*)d_in[14];
    const float* c2r  = (const float*)d_in[15];
    const float* c2b  = (const float*)d_in[16];
    const float* c3w1 = (const float*)d_in[17];
    const float* c3b1 = (const float*)d_in[18];
    const float* c3w2 = (const float*)d_in[19];
    const float* c3b2 = (const float*)d_in[20];
    const float* c3r  = (const float*)d_in[21];
    const float* c3b  = (const float*)d_in[22];
    const float* f1w  = (const float*)d_in[23];
    const float* f1b  = (const float*)d_in[24];
    const float* ow   = (const float*)d_in[25];
    const float* ob   = (const float*)d_in[26];
    float* out = (float*)d_out;

    cudaFuncSetAttribute(mma_gemm_h, cudaFuncAttributeMaxDynamicSharedMemorySize,
                         3 * 128 * (KP_MAX + 8) * (int)sizeof(__half));

    void *pX0, *pA, *pB, *pG, *pAh, *pBTh, *pagg, *pmsg, *ppool;
    cudaGetSymbolAddress(&pX0, g_X0);
    cudaGetSymbolAddress(&pA, g_bufA);
    cudaGetSymbolAddress(&pB, g_bufB);
    cudaGetSymbolAddress(&pG, g_G);
    cudaGetSymbolAddress(&pAh, g_Ah);
    cudaGetSymbolAddress(&pBTh, g_BTh);
    cudaGetSymbolAddress(&pagg, g_agg);
    cudaGetSymbolAddress(&pmsg, g_msg);
    cudaGetSymbolAddress(&ppool, g_pool);
    float* X0  = (float*)pX0;
    float* bufA= (float*)pA;
    float* bufB= (float*)pB;
    __half* G  = (__half*)pG;
    __half* Ah = (__half*)pAh;
    __half* BTh= (__half*)pBTh;
    float* agg = (float*)pagg;
    float* msg = (float*)pmsg;
    float* pool= (float*)ppool;

    build_x0<<<(N_NODES * F0 + 255) / 256, 256>>>(x, pos);
    init_deg<<<(N_NODES + 255) / 256, 256>>>();
    bucket_build<<<(N_EDGES + 255) / 256, 256>>>(ei);
    zero_f<<<(NGR * H2 + 255) / 256, 256>>>(pool, NGR * H2);

    // layer 1: 16 -> 90
    run_layer(X0, bufA, F0, HH, c1w1, c1b1, c1w2, c1b2, c1r, c1b, ea, ei,
              G, Ah, BTh, agg, msg, nullptr, nullptr);
    // layer 2: 90 -> 90
    run_layer(bufA, bufB, HH, HH, c2w1, c2b1, c2w2, c2b2, c2r, c2b, ea, ei,
              G, Ah, BTh, agg, msg, nullptr, nullptr);
    // layer 3: 90 -> 45, fused global_add_pool
    run_layer(bufB, bufA, HH, H2, c3w1, c3b1, c3w2, c3b2, c3r, c3b, ea, ei,
              G, Ah, BTh, agg, msg, bat, pool);

    head_k<<<NGR, 96>>>(f1w, f1b, ow, ob, out);
}